// round 17
// baseline (speedup 1.0000x reference)
#include <cuda_runtime.h>
#include <cuda_bf16.h>
#include <math.h>
#include <stdint.h>

// ---------------------------------------------------------------------------
// Problem constants: B=2, S=2048, E=1024, H=16, D=64
// ---------------------------------------------------------------------------
#define BATCH 2
#define SEQ   2048
#define EMB   1024
#define HEADS 16
#define HDIM  64
#define ROWS  (BATCH * SEQ)        // 4096
#define QKV_N (3 * EMB)            // 3072

// Scratch (allocation-free rule: __device__ globals)
__device__ float g_qkv[ROWS * QKV_N];                    // 48 MB
__device__ float g_attn[ROWS * EMB];                     // 16 MB
// Pre-split K/V, hi/lo INTERLEAVED as uint2 (x=hi pair, y=lo pair)
__device__ uint2 g_khl[BATCH * HEADS * SEQ * 32];        // 16 MB
__device__ uint2 g_vhl[BATCH * HEADS * (SEQ / 2) * 64];  // 16 MB

// ---------------------------------------------------------------------------
// helpers
// ---------------------------------------------------------------------------
__device__ __forceinline__ uint32_t f32_to_tf32(float x) {
    uint32_t r;
    asm("cvt.rna.tf32.f32 %0, %1;" : "=r"(r) : "f"(x));
    return r;
}

__device__ __forceinline__ void mma_tf32_16x8x8(
    float& c0, float& c1, float& c2, float& c3,
    uint32_t a0, uint32_t a1, uint32_t a2, uint32_t a3,
    uint32_t b0, uint32_t b1)
{
    asm volatile(
        "mma.sync.aligned.m16n8k8.row.col.f32.tf32.tf32.f32 "
        "{%0,%1,%2,%3}, {%4,%5,%6,%7}, {%8,%9}, {%0,%1,%2,%3};"
        : "+f"(c0), "+f"(c1), "+f"(c2), "+f"(c3)
        : "r"(a0), "r"(a1), "r"(a2), "r"(a3), "r"(b0), "r"(b1));
}

__device__ __forceinline__ void mma_bf16_16x8x16(
    float& c0, float& c1, float& c2, float& c3,
    uint32_t a0, uint32_t a1, uint32_t a2, uint32_t a3,
    uint32_t b0, uint32_t b1)
{
    asm volatile(
        "mma.sync.aligned.m16n8k16.row.col.f32.bf16.bf16.f32 "
        "{%0,%1,%2,%3}, {%4,%5,%6,%7}, {%8,%9}, {%0,%1,%2,%3};"
        : "+f"(c0), "+f"(c1), "+f"(c2), "+f"(c3)
        : "r"(a0), "r"(a1), "r"(a2), "r"(a3), "r"(b0), "r"(b1));
}

__device__ __forceinline__ uint32_t pack_bf16(float a, float b) {
    __nv_bfloat162 p = __floats2bfloat162_rn(a, b);
    return *reinterpret_cast<uint32_t*>(&p);
}

__device__ __forceinline__ void split_bf16(float x, float& h, float& l) {
    h = __bfloat162float(__float2bfloat16_rn(x));
    l = x - h;
}

__device__ __forceinline__ void cp_async16(void* smem, const void* gmem) {
    uint32_t saddr = (uint32_t)__cvta_generic_to_shared(smem);
    asm volatile("cp.async.cg.shared.global [%0], [%1], 16;"
                 :: "r"(saddr), "l"(gmem));
}
__device__ __forceinline__ void cp_commit() {
    asm volatile("cp.async.commit_group;");
}
__device__ __forceinline__ void cp_wait0() {
    asm volatile("cp.async.wait_group 0;");
}

// ---------------------------------------------------------------------------
// tf32 tensor-core GEMM with fused bias — R6/R9 version (unchanged, passing).
// ---------------------------------------------------------------------------
template<int N, int K>
__device__ __forceinline__ void gemm_tf32(
    const float* __restrict__ A, const float* __restrict__ Bw,
    const float* __restrict__ bias, float* __restrict__ C)
{
    constexpr int BM = 128, BN = 128, BK = 32;
    constexpr int AS = BK + 4;
    constexpr int BS = BN + 8;

    __shared__ uint32_t As[BM * AS];
    __shared__ uint32_t Bs[BK * BS];

    const int tid    = threadIdx.x;
    const int lane   = tid & 31;
    const int wid    = tid >> 5;
    const int warp_m = wid >> 2;
    const int warp_n = wid & 3;
    const int g      = lane >> 2;
    const int t      = lane & 3;

    const int cRow = blockIdx.y * BM;
    const int cCol = blockIdx.x * BN;

    float acc[4][4][4];
    #pragma unroll
    for (int i = 0; i < 4; i++)
        #pragma unroll
        for (int j = 0; j < 4; j++)
            #pragma unroll
            for (int r = 0; r < 4; r++) acc[i][j][r] = 0.f;

    for (int k0 = 0; k0 < K; k0 += BK) {
        #pragma unroll
        for (int i = 0; i < 4; i++) {
            int idx = i * 256 + tid;
            int m   = idx >> 3;
            int c4  = (idx & 7) * 4;
            float4 v = *reinterpret_cast<const float4*>(
                A + (long)(cRow + m) * K + k0 + c4);
            As[m * AS + c4 + 0] = f32_to_tf32(v.x);
            As[m * AS + c4 + 1] = f32_to_tf32(v.y);
            As[m * AS + c4 + 2] = f32_to_tf32(v.z);
            As[m * AS + c4 + 3] = f32_to_tf32(v.w);
        }
        #pragma unroll
        for (int i = 0; i < 4; i++) {
            int idx = i * 256 + tid;
            int kr  = idx >> 5;
            int nc  = (idx & 31) * 4;
            float4 v = *reinterpret_cast<const float4*>(
                Bw + (long)(k0 + kr) * N + cCol + nc);
            Bs[kr * BS + nc + 0] = f32_to_tf32(v.x);
            Bs[kr * BS + nc + 1] = f32_to_tf32(v.y);
            Bs[kr * BS + nc + 2] = f32_to_tf32(v.z);
            Bs[kr * BS + nc + 3] = f32_to_tf32(v.w);
        }
        __syncthreads();

        #pragma unroll
        for (int kk = 0; kk < 4; kk++) {
            const int k8 = kk * 8;
            uint32_t a[4][4];
            #pragma unroll
            for (int ma = 0; ma < 4; ma++) {
                int row = warp_m * 64 + ma * 16;
                a[ma][0] = As[(row + g) * AS + k8 + t];
                a[ma][1] = As[(row + g + 8) * AS + k8 + t];
                a[ma][2] = As[(row + g) * AS + k8 + t + 4];
                a[ma][3] = As[(row + g + 8) * AS + k8 + t + 4];
            }
            uint32_t b[4][2];
            #pragma unroll
            for (int na = 0; na < 4; na++) {
                int col = warp_n * 32 + na * 8 + g;
                b[na][0] = Bs[(k8 + t) * BS + col];
                b[na][1] = Bs[(k8 + t + 4) * BS + col];
            }
            #pragma unroll
            for (int ma = 0; ma < 4; ma++)
                #pragma unroll
                for (int na = 0; na < 4; na++)
                    mma_tf32_16x8x8(acc[ma][na][0], acc[ma][na][1],
                                    acc[ma][na][2], acc[ma][na][3],
                                    a[ma][0], a[ma][1], a[ma][2], a[ma][3],
                                    b[na][0], b[na][1]);
        }
        __syncthreads();
    }

    #pragma unroll
    for (int ma = 0; ma < 4; ma++) {
        #pragma unroll
        for (int na = 0; na < 4; na++) {
            int row = cRow + warp_m * 64 + ma * 16 + g;
            int col = cCol + warp_n * 32 + na * 8 + 2 * t;
            float2 bv = *reinterpret_cast<const float2*>(bias + col);
            float2 v0, v1;
            v0.x = acc[ma][na][0] + bv.x;
            v0.y = acc[ma][na][1] + bv.y;
            v1.x = acc[ma][na][2] + bv.x;
            v1.y = acc[ma][na][3] + bv.y;
            *reinterpret_cast<float2*>(C + (long)row * N + col)       = v0;
            *reinterpret_cast<float2*>(C + (long)(row + 8) * N + col) = v1;
        }
    }
}

__global__ __launch_bounds__(256) void qkv_tf32_kernel(
    const float* __restrict__ A, const float* __restrict__ Bw,
    const float* __restrict__ bias)
{
    gemm_tf32<QKV_N, EMB>(A, Bw, bias, g_qkv);
}

__global__ __launch_bounds__(256) void proj_tf32_kernel(
    const float* __restrict__ Bw, const float* __restrict__ bias,
    float* __restrict__ C)
{
    gemm_tf32<EMB, EMB>(g_attn, Bw, bias, C);
}

// ---------------------------------------------------------------------------
// Presplit kernels: write hi/lo INTERLEAVED uint2 (x = packed hi pair,
// y = packed lo pair) so attention frag loads become single LDS.64.
// ---------------------------------------------------------------------------
__global__ __launch_bounds__(256) void presplit_k_kernel()
{
    const int r   = blockIdx.x;                // b*SEQ + s
    const int b   = r >> 11, s = r & (SEQ - 1);
    const int dg  = threadIdx.x * 4;           // 0..1020
    const int h   = dg >> 6, d = dg & 63;
    float4 v = *reinterpret_cast<const float4*>(g_qkv + (long)r * QKV_N + EMB + dg);
    float h0, l0, h1, l1, h2, l2, h3, l3;
    split_bf16(v.x, h0, l0); split_bf16(v.y, h1, l1);
    split_bf16(v.z, h2, l2); split_bf16(v.w, h3, l3);
    long o = ((long)(b * HEADS + h) * SEQ + s) * 32 + (d >> 1);   // uint2 idx
    uint4 val;
    val.x = pack_bf16(h0, h1);  val.y = pack_bf16(l0, l1);
    val.z = pack_bf16(h2, h3);  val.w = pack_bf16(l2, l3);
    *reinterpret_cast<uint4*>(g_khl + o) = val;
}

__global__ __launch_bounds__(256) void presplit_v_kernel()
{
    const int p   = blockIdx.x;                // b*(SEQ/2) + sp
    const int b   = p >> 10, sp = p & (SEQ / 2 - 1);
    const int dg  = threadIdx.x * 4;
    const int h   = dg >> 6, d = dg & 63;
    const long rbase = (long)(b * SEQ + 2 * sp) * QKV_N + 2 * EMB + dg;
    float4 v0 = *reinterpret_cast<const float4*>(g_qkv + rbase);
    float4 v1 = *reinterpret_cast<const float4*>(g_qkv + rbase + QKV_N);
    float ha, la, hb, lb;
    long o = ((long)(b * HEADS + h) * (SEQ / 2) + sp) * 64 + d;   // uint2 idx
    uint4 q0, q1;
    split_bf16(v0.x, ha, la); split_bf16(v1.x, hb, lb);
    q0.x = pack_bf16(ha, hb); q0.y = pack_bf16(la, lb);
    split_bf16(v0.y, ha, la); split_bf16(v1.y, hb, lb);
    q0.z = pack_bf16(ha, hb); q0.w = pack_bf16(la, lb);
    split_bf16(v0.z, ha, la); split_bf16(v1.z, hb, lb);
    q1.x = pack_bf16(ha, hb); q1.y = pack_bf16(la, lb);
    split_bf16(v0.w, ha, la); split_bf16(v1.w, hb, lb);
    q1.z = pack_bf16(ha, hb); q1.w = pack_bf16(la, lb);
    *reinterpret_cast<uint4*>(g_vhl + o)     = q0;
    *reinterpret_cast<uint4*>(g_vhl + o + 2) = q1;
}

// ---------------------------------------------------------------------------
// Flash attention: 32-key tiles, cp.async double-buffered smem, 2 CTAs/SM,
// term-outer bf16-split mma, hi/lo-interleaved smem -> LDS.64 frag loads.
// Math identical to R14.
// ---------------------------------------------------------------------------
#define KW2 36   // uint2 per key row (32 data + 4 pad)
#define VW2 72   // uint2 per pair row (64 data + 8 pad)
#define KTILE 32

__global__ __launch_bounds__(256, 2) void flash_attn_mma_kernel()
{
    const int qt   = (int)gridDim.x - 1 - (int)blockIdx.x;  // heavy blocks first
    const int h    = blockIdx.y;
    const int b    = blockIdx.z;
    const int tid  = threadIdx.x;
    const int lane = tid & 31;
    const int w    = tid >> 5;
    const int g    = lane >> 2;   // 0..7
    const int t    = lane & 3;    // 0..3

    const int qbase = qt * 128;
    const int row0  = qbase + w * 16 + g;
    const int hoff  = h * HDIM;

    // double-buffered tiles: 2*(32*36 + 16*72)*8 = 36,864 B
    __shared__ uint2 Khl[2][KTILE * KW2];
    __shared__ uint2 Vhl[2][(KTILE / 2) * VW2];

    uint32_t qh[4][4], ql[4][4];
    {
        const long r0 = (long)(b * SEQ + row0) * QKV_N + hoff;
        const long r1 = r0 + 8L * QKV_N;
        #pragma unroll
        for (int kk = 0; kk < 4; kk++) {
            int d0 = kk * 16 + 2 * t;
            int d1 = d0 + 8;
            float hx, lx, hy, ly;
            split_bf16(g_qkv[r0 + d0] * 0.125f, hx, lx);
            split_bf16(g_qkv[r0 + d0 + 1] * 0.125f, hy, ly);
            qh[kk][0] = pack_bf16(hx, hy);  ql[kk][0] = pack_bf16(lx, ly);
            split_bf16(g_qkv[r1 + d0] * 0.125f, hx, lx);
            split_bf16(g_qkv[r1 + d0 + 1] * 0.125f, hy, ly);
            qh[kk][1] = pack_bf16(hx, hy);  ql[kk][1] = pack_bf16(lx, ly);
            split_bf16(g_qkv[r0 + d1] * 0.125f, hx, lx);
            split_bf16(g_qkv[r0 + d1 + 1] * 0.125f, hy, ly);
            qh[kk][2] = pack_bf16(hx, hy);  ql[kk][2] = pack_bf16(lx, ly);
            split_bf16(g_qkv[r1 + d1] * 0.125f, hx, lx);
            split_bf16(g_qkv[r1 + d1 + 1] * 0.125f, hy, ly);
            qh[kk][3] = pack_bf16(hx, hy);  ql[kk][3] = pack_bf16(lx, ly);
        }
    }

    float o[8][4];
    #pragma unroll
    for (int na = 0; na < 8; na++)
        #pragma unroll
        for (int e = 0; e < 4; e++) o[na][e] = 0.f;
    float m0 = -INFINITY, m1 = -INFINITY, l0 = 0.f, l1 = 0.f;

    const long khbase = (long)(b * HEADS + h) * SEQ * 32;          // uint2 units
    const long vbase0 = (long)(b * HEADS + h) * (SEQ / 2) * 64;    // uint2 units

    auto fill = [&](int kt, int bufi) {
        const long kb = khbase + (long)kt * KTILE * 32;
        #pragma unroll
        for (int i = 0; i < 2; i++) {
            int idx = i * 256 + tid;
            int j   = idx >> 4;            // key row 0..31
            int c   = (idx & 15) * 2;      // uint2 col (2 per cp)
            cp_async16(&Khl[bufi][j * KW2 + c], g_khl + kb + j * 32 + c);
        }
        const long vb = vbase0 + (long)kt * (KTILE / 2) * 64;
        #pragma unroll
        for (int i = 0; i < 2; i++) {
            int idx = i * 256 + tid;
            int jp  = idx >> 5;            // pair row 0..15
            int c   = (idx & 31) * 2;      // uint2 col
            cp_async16(&Vhl[bufi][jp * VW2 + c], g_vhl + vb + jp * 64 + c);
        }
        cp_commit();
    };

    const int ntiles = 4 * qt + 4;
    fill(0, 0);
    int buf = 0;

    for (int kt = 0; kt < ntiles; kt++) {
        cp_wait0();
        __syncthreads();
        if (kt + 1 < ntiles) fill(kt + 1, buf ^ 1);

        // ---- scores S = Q K^T (3-term bf16 split, term-outer, LDS.64) ----
        float s[4][4];
        #pragma unroll
        for (int na = 0; na < 4; na++)
            #pragma unroll
            for (int e = 0; e < 4; e++) s[na][e] = 0.f;

        #pragma unroll
        for (int kk = 0; kk < 4; kk++) {
            const int w0 = kk * 8 + t;
            uint2 k0[4], k1[4];
            #pragma unroll
            for (int na = 0; na < 4; na++) {
                int key = na * 8 + g;
                k0[na] = Khl[buf][key * KW2 + w0];
                k1[na] = Khl[buf][key * KW2 + w0 + 4];
            }
            #pragma unroll
            for (int na = 0; na < 4; na++)
                mma_bf16_16x8x16(s[na][0], s[na][1], s[na][2], s[na][3],
                                 qh[kk][0], qh[kk][1], qh[kk][2], qh[kk][3],
                                 k0[na].x, k1[na].x);
            #pragma unroll
            for (int na = 0; na < 4; na++)
                mma_bf16_16x8x16(s[na][0], s[na][1], s[na][2], s[na][3],
                                 ql[kk][0], ql[kk][1], ql[kk][2], ql[kk][3],
                                 k0[na].x, k1[na].x);
            #pragma unroll
            for (int na = 0; na < 4; na++)
                mma_bf16_16x8x16(s[na][0], s[na][1], s[na][2], s[na][3],
                                 qh[kk][0], qh[kk][1], qh[kk][2], qh[kk][3],
                                 k0[na].y, k1[na].y);
        }

        // ---- causal mask (diagonal tiles: last 4) ----
        if (kt >= 4 * qt) {
            const int colbase = kt * KTILE + 2 * t;
            #pragma unroll
            for (int na = 0; na < 4; na++) {
                int c = colbase + 8 * na;
                if (c     > row0)     s[na][0] = -INFINITY;
                if (c + 1 > row0)     s[na][1] = -INFINITY;
                if (c     > row0 + 8) s[na][2] = -INFINITY;
                if (c + 1 > row0 + 8) s[na][3] = -INFINITY;
            }
        }

        // ---- online softmax ----
        float tm0 = -INFINITY, tm1 = -INFINITY;
        #pragma unroll
        for (int na = 0; na < 4; na++) {
            tm0 = fmaxf(tm0, fmaxf(s[na][0], s[na][1]));
            tm1 = fmaxf(tm1, fmaxf(s[na][2], s[na][3]));
        }
        tm0 = fmaxf(tm0, __shfl_xor_sync(0xffffffffu, tm0, 1));
        tm0 = fmaxf(tm0, __shfl_xor_sync(0xffffffffu, tm0, 2));
        tm1 = fmaxf(tm1, __shfl_xor_sync(0xffffffffu, tm1, 1));
        tm1 = fmaxf(tm1, __shfl_xor_sync(0xffffffffu, tm1, 2));

        float mn0 = fmaxf(m0, tm0), mn1 = fmaxf(m1, tm1);
        float a0 = __expf(m0 - mn0), a1 = __expf(m1 - mn1);
        l0 *= a0; l1 *= a1;
        #pragma unroll
        for (int na = 0; na < 8; na++) {
            o[na][0] *= a0; o[na][1] *= a0;
            o[na][2] *= a1; o[na][3] *= a1;
        }

        float rs0 = 0.f, rs1 = 0.f;
        #pragma unroll
        for (int na = 0; na < 4; na++) {
            s[na][0] = __expf(s[na][0] - mn0);
            s[na][1] = __expf(s[na][1] - mn0);
            s[na][2] = __expf(s[na][2] - mn1);
            s[na][3] = __expf(s[na][3] - mn1);
            rs0 += s[na][0] + s[na][1];
            rs1 += s[na][2] + s[na][3];
        }
        rs0 += __shfl_xor_sync(0xffffffffu, rs0, 1);
        rs0 += __shfl_xor_sync(0xffffffffu, rs0, 2);
        rs1 += __shfl_xor_sync(0xffffffffu, rs1, 1);
        rs1 += __shfl_xor_sync(0xffffffffu, rs1, 2);
        l0 += rs0; l1 += rs1;
        m0 = mn0; m1 = mn1;

        // ---- O += P V (S C-frag IS P A-frag; 3-term split, term-outer,
        //      LDS.64 V frags, na processed in two halves of 4) ----
        #pragma unroll
        for (int kk = 0; kk < 2; kk++) {
            const int n0 = 2 * kk;
            float h0, lo0, h1, lo1;
            uint32_t ph[4], pl[4];
            split_bf16(s[n0][0], h0, lo0);  split_bf16(s[n0][1], h1, lo1);
            ph[0] = pack_bf16(h0, h1);      pl[0] = pack_bf16(lo0, lo1);
            split_bf16(s[n0][2], h0, lo0);  split_bf16(s[n0][3], h1, lo1);
            ph[1] = pack_bf16(h0, h1);      pl[1] = pack_bf16(lo0, lo1);
            split_bf16(s[n0 + 1][0], h0, lo0);  split_bf16(s[n0 + 1][1], h1, lo1);
            ph[2] = pack_bf16(h0, h1);      pl[2] = pack_bf16(lo0, lo1);
            split_bf16(s[n0 + 1][2], h0, lo0);  split_bf16(s[n0 + 1][3], h1, lo1);
            ph[3] = pack_bf16(h0, h1);      pl[3] = pack_bf16(lo0, lo1);

            const int r0w = (8 * kk + t) * VW2;
            const int r1w = (8 * kk + t + 4) * VW2;
            #pragma unroll
            for (int half = 0; half < 2; half++) {
                const int nab = half * 4;
                uint2 v0[4], v1[4];
                #pragma unroll
                for (int na = 0; na < 4; na++) {
                    int col = (nab + na) * 8 + g;
                    v0[na] = Vhl[buf][r0w + col];
                    v1[na] = Vhl[buf][r1w + col];
                }
                #pragma unroll
                for (int na = 0; na < 4; na++)
                    mma_bf16_16x8x16(o[nab + na][0], o[nab + na][1],
                                     o[nab + na][2], o[nab + na][3],
                                     ph[0], ph[1], ph[2], ph[3],
                                     v0[na].x, v1[na].x);
                #pragma unroll
                for (int na = 0; na < 4; na++)
                    mma_bf16_16x8x16(o[nab + na][0], o[nab + na][1],
                                     o[nab + na][2], o[nab + na][3],
                                     pl[0], pl[1], pl[2], pl[3],
                                     v0[na].x, v1[na].x);
                #pragma unroll
                for (int na = 0; na < 4; na++)
                    mma_bf16_16x8x16(o[nab + na][0], o[nab + na][1],
                                     o[nab + na][2], o[nab + na][3],
                                     ph[0], ph[1], ph[2], ph[3],
                                     v0[na].y, v1[na].y);
            }
        }
        buf ^= 1;
    }

    const float inv0 = 1.f / l0, inv1 = 1.f / l1;
    const long ob0 = (long)(b * SEQ + row0) * EMB + hoff;
    const long ob1 = ob0 + 8L * EMB;
    #pragma unroll
    for (int na = 0; na < 8; na++) {
        int col = na * 8 + 2 * t;
        float2 w0 = make_float2(o[na][0] * inv0, o[na][1] * inv0);
        float2 w1 = make_float2(o[na][2] * inv1, o[na][3] * inv1);
        *reinterpret_cast<float2*>(g_attn + ob0 + col) = w0;
        *reinterpret_cast<float2*>(g_attn + ob1 + col) = w1;
    }
}

// ---------------------------------------------------------------------------
// Launch: five kernel launches, nothing else.
// ---------------------------------------------------------------------------
extern "C" void kernel_launch(void* const* d_in, const int* in_sizes, int n_in,
                              void* d_out, int out_size)
{
    const float* hidden = (const float*)d_in[0];
    const float* w_attn = (const float*)d_in[1];
    const float* b_attn = (const float*)d_in[2];
    const float* w_proj = (const float*)d_in[3];
    const float* b_proj = (const float*)d_in[4];
    float* out = (float*)d_out;

    // 1) QKV projection (tf32 TC) -> g_qkv
    qkv_tf32_kernel<<<dim3(QKV_N / 128, ROWS / 128), 256>>>(hidden, w_attn, b_attn);

    // 2) Presplit K/V into interleaved bf16 hi/lo uint2 layout
    presplit_k_kernel<<<ROWS, 256>>>();
    presplit_v_kernel<<<ROWS / 2, 256>>>();

    // 3) Causal MHA flash attention (LDS.64 frags, cp.async, occ 2) -> g_attn
    flash_attn_mma_kernel<<<dim3(SEQ / 128, HEADS, BATCH), 256>>>();

    // 4) Output projection (tf32 TC) -> out
    proj_tf32_kernel<<<dim3(EMB / 128, ROWS / 128), 256>>>(w_proj, b_proj, out);
}